// round 6
// baseline (speedup 1.0000x reference)
#include <cuda_runtime.h>
#include <cuda_bf16.h>

#define B_  128
#define T_  500
#define C_  700
#define CP_ 704            // C padded to multiple of 16 (zero-filled)
#define H_  1024
#define O_  20
#define M_  (B_*T_)        // 64000 rows for the input GEMM

// ---------------- scratch (static device arrays; no allocation) ----------------
__device__ float g_xd  [M_ * CP_];   // delayed input, [b*T+t][c]      (~180 MB)
__device__ float g_I   [M_ * H_];    // I_in = xd @ w_in^T, [b*T+t][h] (~262 MB)
__device__ float g_winT[CP_ * H_];   // w_in transposed [c][h], zero-padded rows
__device__ float g_wrecT[H_ * H_];   // w_rec transposed [j][h]

// streaming (evict-first) load/store hints — keep w_recT L2-resident
__device__ __forceinline__ float ldcs(const float* p) {
    float v; asm volatile("ld.global.cs.f32 %0, [%1];" : "=f"(v) : "l"(p)); return v;
}
__device__ __forceinline__ void stcs4(float* p, float4 v) {
    asm volatile("st.global.cs.v4.f32 [%0], {%1,%2,%3,%4};"
                 :: "l"(p), "f"(v.x), "f"(v.y), "f"(v.z), "f"(v.w));
}

// ---------------- prep: transposes ----------------
__global__ void prep_kernel(const float* __restrict__ w_in,
                            const float* __restrict__ w_rec) {
    int i = blockIdx.x * blockDim.x + threadIdx.x;
    const int NW = CP_ * H_;
    if (i < NW) {
        int c = i >> 10, h = i & 1023;
        g_winT[i] = (c < C_) ? __ldg(&w_in[h * C_ + c]) : 0.0f;
    } else {
        int j = i - NW;
        if (j < H_ * H_) {
            int r = j >> 10, h = j & 1023;
            g_wrecT[j] = __ldg(&w_rec[h * H_ + r]);
        }
    }
}

// ---------------- delay gather: xd[b][t][c] = x[b][t - d_c][c] ----------------
// one thread = 4 consecutive channels; float4 store
__global__ void gather_kernel(const float* __restrict__ x,
                              const int* __restrict__ delays) {
    int i = blockIdx.x * blockDim.x + threadIdx.x;
    if (i >= M_ * (CP_ / 4)) return;
    int c4 = (i % (CP_ / 4)) * 4;
    int bt = i / (CP_ / 4);
    int t  = bt % T_;
    int b  = bt / T_;
    const float* xb = x + (size_t)b * T_ * C_;
    float4 v = make_float4(0.f, 0.f, 0.f, 0.f);
#pragma unroll
    for (int k = 0; k < 4; k++) {
        int c = c4 + k;
        float val = 0.0f;
        if (c < C_) {
            int ts = t - __ldg(&delays[c]);
            if (ts >= 0) val = __ldg(&xb[(size_t)ts * C_ + c]);
        }
        ((float*)&v)[k] = val;
    }
    *(float4*)(g_xd + (size_t)bt * CP_ + c4) = v;
}

// ---------------- packed f32x2 helpers (FFMA2 on sm_103a) ----------------
__device__ __forceinline__ unsigned long long pk2(float lo, float hi) {
    unsigned long long r;
    asm("mov.b64 %0, {%1,%2};" : "=l"(r) : "f"(lo), "f"(hi));
    return r;
}
__device__ __forceinline__ void fma2(unsigned long long& c,
                                     unsigned long long a,
                                     unsigned long long b) {
    asm("fma.rn.f32x2 %0, %1, %2, %3;" : "=l"(c) : "l"(a), "l"(b), "l"(c));
}
__device__ __forceinline__ float2 upk2(unsigned long long p) {
    float lo, hi;
    asm("mov.b64 {%0,%1}, %2;" : "=f"(lo), "=f"(hi) : "l"(p));
    return make_float2(lo, hi);
}

// ---------------- GEMM: g_I = g_xd (64000x704) * g_winT (704x1024) ----------------
// 128x128 tile, BK=16, 256 threads, 8x8 per-thread microtile, double-buffered smem,
// inner product via packed fma.rn.f32x2 (n-paired accumulators).
#define ASTRIDE 136   // padded row stride for As to kill STS bank conflicts

__global__ void __launch_bounds__(256) gemm_kernel() {
    __shared__ float As[2][16][ASTRIDE];
    __shared__ float Bs[2][16][128];
    int tid = threadIdx.x;
    int mBase = blockIdx.y * 128;
    int nBase = blockIdx.x * 128;
    const float* Ag = g_xd  + (size_t)mBase * CP_;
    const float* Bg = g_winT + nBase;

    int arow = tid >> 2;           // 0..63  (row within 128-tile, +64 for second)
    int akc  = (tid & 3) * 4;      // k offset (float) within 16
    int bk   = tid >> 5;           // 0..7   (k row, +8 for second)
    int bc   = (tid & 31) * 4;     // n offset

    float4 a0v, a1v, b0v, b1v;
    a0v = *(const float4*)(Ag + (size_t)arow      * CP_ + akc);
    a1v = *(const float4*)(Ag + (size_t)(arow+64) * CP_ + akc);
    b0v = *(const float4*)(Bg + (size_t)bk      * H_ + bc);
    b1v = *(const float4*)(Bg + (size_t)(bk+8)  * H_ + bc);

    As[0][akc+0][arow] = a0v.x; As[0][akc+1][arow] = a0v.y;
    As[0][akc+2][arow] = a0v.z; As[0][akc+3][arow] = a0v.w;
    As[0][akc+0][arow+64] = a1v.x; As[0][akc+1][arow+64] = a1v.y;
    As[0][akc+2][arow+64] = a1v.z; As[0][akc+3][arow+64] = a1v.w;
    *(float4*)&Bs[0][bk][bc]   = b0v;
    *(float4*)&Bs[0][bk+8][bc] = b1v;
    __syncthreads();

    unsigned long long acc[8][4];
#pragma unroll
    for (int i = 0; i < 8; i++)
#pragma unroll
        for (int j = 0; j < 4; j++) acc[i][j] = 0ull;

    int tn = (tid & 15) * 8;
    int tm = (tid >> 4) * 8;

    const int KT = CP_ / 16;   // 44
    for (int kt = 0; kt < KT; kt++) {
        int cur = kt & 1;
        if (kt + 1 < KT) {
            int k0 = (kt + 1) * 16;
            a0v = *(const float4*)(Ag + (size_t)arow      * CP_ + k0 + akc);
            a1v = *(const float4*)(Ag + (size_t)(arow+64) * CP_ + k0 + akc);
            b0v = *(const float4*)(Bg + (size_t)(k0+bk)   * H_ + bc);
            b1v = *(const float4*)(Bg + (size_t)(k0+bk+8) * H_ + bc);
        }
#pragma unroll
        for (int kk = 0; kk < 16; kk++) {
            float4 af0 = *(const float4*)&As[cur][kk][tm];
            float4 af1 = *(const float4*)&As[cur][kk][tm+4];
            float4 bf0 = *(const float4*)&Bs[cur][kk][tn];
            float4 bf1 = *(const float4*)&Bs[cur][kk][tn+4];
            unsigned long long bp0 = pk2(bf0.x, bf0.y);
            unsigned long long bp1 = pk2(bf0.z, bf0.w);
            unsigned long long bp2 = pk2(bf1.x, bf1.y);
            unsigned long long bp3 = pk2(bf1.z, bf1.w);
            float aa[8] = {af0.x, af0.y, af0.z, af0.w, af1.x, af1.y, af1.z, af1.w};
#pragma unroll
            for (int i = 0; i < 8; i++) {
                unsigned long long ad = pk2(aa[i], aa[i]);
                fma2(acc[i][0], ad, bp0);
                fma2(acc[i][1], ad, bp1);
                fma2(acc[i][2], ad, bp2);
                fma2(acc[i][3], ad, bp3);
            }
        }
        if (kt + 1 < KT) {
            int nxt = cur ^ 1;
            As[nxt][akc+0][arow] = a0v.x; As[nxt][akc+1][arow] = a0v.y;
            As[nxt][akc+2][arow] = a0v.z; As[nxt][akc+3][arow] = a0v.w;
            As[nxt][akc+0][arow+64] = a1v.x; As[nxt][akc+1][arow+64] = a1v.y;
            As[nxt][akc+2][arow+64] = a1v.z; As[nxt][akc+3][arow+64] = a1v.w;
            *(float4*)&Bs[nxt][bk][bc]   = b0v;
            *(float4*)&Bs[nxt][bk+8][bc] = b1v;
            __syncthreads();
        }
    }

    // streaming (evict-first) stores: g_I is written once, read once later;
    // keep it from thrashing L2 where w_recT must stay resident.
    float* Cg = g_I + (size_t)(mBase + tm) * H_ + nBase + tn;
#pragma unroll
    for (int i = 0; i < 8; i++) {
        float2 r0 = upk2(acc[i][0]), r1 = upk2(acc[i][1]);
        float2 r2 = upk2(acc[i][2]), r3 = upk2(acc[i][3]);
        stcs4(Cg + (size_t)i * H_,     make_float4(r0.x, r0.y, r1.x, r1.y));
        stcs4(Cg + (size_t)i * H_ + 4, make_float4(r2.x, r2.y, r3.x, r3.y));
    }
}

// ---------------- recurrent scan: one CTA per batch sample ----------------
// thread = neuron h; v/a/spk in registers. Per step: spikes balloted into a
// 32-word mask; warp 31 compacts set bits into a counted index list
// (double-buffered); next step's rec input walks the list with 8 independent
// accumulators (MLP=8 on L2-resident w_recT rows). g_I loads are software-
// pipelined one step ahead to hide DRAM latency under the list walk + syncs.
__global__ void __launch_bounds__(1024) rec_kernel(
    const float* __restrict__ w_out,  const float* __restrict__ alpha,
    const float* __restrict__ rho,    const float* __restrict__ beta_a,
    const float* __restrict__ beta_out, float* __restrict__ out) {
    __shared__ unsigned smask[32];
    __shared__ short    slist[2][H_];
    __shared__ int      scnt[2];
    int tid  = threadIdx.x;
    int b    = blockIdx.x;
    int lane = tid & 31, wid = tid >> 5;
    int h = tid;

    float al = __ldg(&alpha[h]), rh = __ldg(&rho[h]), ba = __ldg(&beta_a[h]);
    float one_al = 1.0f - al, one_rh = 1.0f - rh;
    float bo = 0.0f, one_bo = 0.0f;
    if (wid < O_) { bo = __ldg(&beta_out[wid]); one_bo = 1.0f - bo; }

    float v = 0.0f, a = 0.0f, spk = 0.0f;
    float vo = 0.0f, osum = 0.0f;
    if (tid == 0) { scnt[0] = 0; scnt[1] = 0; }
    __syncthreads();

    const float* Ib = g_I + (size_t)b * T_ * H_ + h;
    const float* Wr = g_wrecT + h;
    const float* Wo = w_out + wid * H_ + lane;

    float Icur = ldcs(Ib);                   // prefetched I for t=0

    for (int t = 0; t < T_; t++) {
        int q = t & 1;
        // issue next step's g_I load early; retires under list walk + syncs
        float Inxt = 0.0f;
        if (t + 1 < T_) Inxt = ldcs(Ib + (size_t)(t + 1) * H_);

        float acc = Icur;

        // recurrent input: walk previous-step spike index list, 8-way MLP
        int cnt = scnt[q];
        if (cnt > 0) {
            const short* lp = slist[q];
            float s0 = 0.f, s1 = 0.f, s2 = 0.f, s3 = 0.f;
            float s4 = 0.f, s5 = 0.f, s6 = 0.f, s7 = 0.f;
            int j = 0;
            for (; j + 8 <= cnt; j += 8) {
                int i0 = lp[j+0], i1 = lp[j+1], i2 = lp[j+2], i3 = lp[j+3];
                int i4 = lp[j+4], i5 = lp[j+5], i6 = lp[j+6], i7 = lp[j+7];
                s0 += __ldg(Wr + ((size_t)i0 << 10));
                s1 += __ldg(Wr + ((size_t)i1 << 10));
                s2 += __ldg(Wr + ((size_t)i2 << 10));
                s3 += __ldg(Wr + ((size_t)i3 << 10));
                s4 += __ldg(Wr + ((size_t)i4 << 10));
                s5 += __ldg(Wr + ((size_t)i5 << 10));
                s6 += __ldg(Wr + ((size_t)i6 << 10));
                s7 += __ldg(Wr + ((size_t)i7 << 10));
            }
#pragma unroll 1
            for (; j < cnt; j++)
                s0 += __ldg(Wr + ((size_t)lp[j] << 10));
            acc += ((s0 + s1) + (s2 + s3)) + ((s4 + s5) + (s6 + s7));
        }

        // adaptive LIF update (same expression order as reference)
        float v1n  = al * v * (1.0f - spk) + one_al * (acc - a);
        float spkn = ((v1n - 1.0f) > 0.0f) ? 1.0f : 0.0f;
        a = rh * a + one_rh * (ba * v1n + spkn);
        v = v1n; spk = spkn;

        unsigned bal = __ballot_sync(0xffffffffu, spkn != 0.0f);
        if (lane == 0) smask[wid] = bal;
        __syncthreads();   // masks complete

        if (wid == 31) {
            // compact masks into index list for next step (warp scan + extract)
            unsigned m = smask[lane];
            int c = __popc(m);
            int pre = c;
#pragma unroll
            for (int o = 1; o < 32; o <<= 1) {
                int vv = __shfl_up_sync(0xffffffffu, pre, o);
                if (lane >= o) pre += vv;
            }
            int base = pre - c;
            int qn = q ^ 1;
            unsigned mm = m; int k = base;
            while (mm) {
                int bit = __ffs(mm) - 1;
                mm &= mm - 1;
                slist[qn][k++] = (short)((lane << 5) + bit);
            }
            if (lane == 31) scnt[qn] = pre;
        } else if (wid < O_) {
            // output layer: warp o computes I_out[o] = sum over spiking h of w_out[o][h]
            float io = 0.0f;
#pragma unroll 8
            for (int w = 0; w < 32; w++) {
                unsigned mm = smask[w];
                if (mm) {   // skip empty mask words (uniform branch, saves LSU slots)
                    float bit = (float)((mm >> lane) & 1u);
                    io += bit * __ldg(Wo + (w << 5));
                }
            }
#pragma unroll
            for (int off = 16; off; off >>= 1)
                io += __shfl_xor_sync(0xffffffffu, io, off);
            if (lane == 0) { vo = bo * vo + one_bo * io; osum += vo; }
        }
        __syncthreads();   // list ready for next step
        Icur = Inxt;
    }
    if (wid < O_ && lane == 0) out[b * O_ + wid] = osum / (float)T_;
}

// ---------------- launch ----------------
extern "C" void kernel_launch(void* const* d_in, const int* in_sizes, int n_in,
                              void* d_out, int out_size) {
    const float* x        = (const float*)d_in[0];
    const int*   delays   = (const int*)  d_in[1];
    const float* w_in     = (const float*)d_in[2];
    const float* w_rec    = (const float*)d_in[3];
    const float* w_out    = (const float*)d_in[4];
    const float* alpha    = (const float*)d_in[5];
    const float* rho      = (const float*)d_in[6];
    const float* beta_a   = (const float*)d_in[7];
    const float* beta_out = (const float*)d_in[8];
    float* out = (float*)d_out;

    int prep_n = CP_ * H_ + H_ * H_;
    prep_kernel  <<<(prep_n + 511) / 512, 512>>>(w_in, w_rec);
    gather_kernel<<<(M_ * (CP_ / 4) + 511) / 512, 512>>>(x, delays);
    gemm_kernel  <<<dim3(8, 500), 256>>>();
    rec_kernel   <<<B_, 1024>>>(w_out, alpha, rho, beta_a, beta_out, out);
}

// round 16
// speedup vs baseline: 1.4762x; 1.4762x over previous
#include <cuda_runtime.h>
#include <cuda_bf16.h>

#define B_  128
#define T_  500
#define C_  700
#define CP_ 704            // C padded to multiple of 16 (zero-filled)
#define H_  1024
#define O_  20
#define M_  (B_*T_)        // 64000 rows for the input GEMM

// ---------------- scratch (static device arrays; no allocation) ----------------
__device__ float g_xd   [M_ * CP_];   // delayed input, [b*T+t][c]
__device__ float g_I    [M_ * H_];    // I_in = xd @ w_in^T, [b*T+t][h]
__device__ float g_winT [CP_ * H_];   // w_in transposed [c][h], zero-padded rows
__device__ float g_wrecT[H_ * H_];    // w_rec transposed [j][h]
__device__ float g_woutT[H_ * O_];    // w_out transposed [j][o]

// ---------------- prep: transposes ----------------
__global__ void prep_kernel(const float* __restrict__ w_in,
                            const float* __restrict__ w_rec,
                            const float* __restrict__ w_out) {
    int i = blockIdx.x * blockDim.x + threadIdx.x;
    const int NW = CP_ * H_;
    const int NR = H_ * H_;
    if (i < NW) {
        int c = i >> 10, h = i & 1023;
        g_winT[i] = (c < C_) ? __ldg(&w_in[h * C_ + c]) : 0.0f;
    } else if (i < NW + NR) {
        int j = i - NW;
        int r = j >> 10, h = j & 1023;
        g_wrecT[j] = __ldg(&w_rec[h * H_ + r]);
    } else {
        int j2 = i - NW - NR;
        if (j2 < H_ * O_) {
            int j = j2 / O_, o = j2 % O_;
            g_woutT[j2] = __ldg(&w_out[o * H_ + j]);
        }
    }
}

// ---------------- delay gather: xd[b][t][c] = x[b][t - d_c][c] ----------------
__global__ void gather_kernel(const float* __restrict__ x,
                              const int* __restrict__ delays) {
    int i = blockIdx.x * blockDim.x + threadIdx.x;
    if (i >= M_ * (CP_ / 4)) return;
    int c4 = (i % (CP_ / 4)) * 4;
    int bt = i / (CP_ / 4);
    int t  = bt % T_;
    int b  = bt / T_;
    const float* xb = x + (size_t)b * T_ * C_;
    float4 v = make_float4(0.f, 0.f, 0.f, 0.f);
#pragma unroll
    for (int k = 0; k < 4; k++) {
        int c = c4 + k;
        float val = 0.0f;
        if (c < C_) {
            int ts = t - __ldg(&delays[c]);
            if (ts >= 0) val = __ldg(&xb[(size_t)ts * C_ + c]);
        }
        ((float*)&v)[k] = val;
    }
    *(float4*)(g_xd + (size_t)bt * CP_ + c4) = v;
}

// ---------------- packed f32x2 helpers (FFMA2 on sm_103a) ----------------
__device__ __forceinline__ unsigned long long pk2(float lo, float hi) {
    unsigned long long r;
    asm("mov.b64 %0, {%1,%2};" : "=l"(r) : "f"(lo), "f"(hi));
    return r;
}
__device__ __forceinline__ void fma2(unsigned long long& c,
                                     unsigned long long a,
                                     unsigned long long b) {
    asm("fma.rn.f32x2 %0, %1, %2, %3;" : "=l"(c) : "l"(a), "l"(b), "l"(c));
}
__device__ __forceinline__ float2 upk2(unsigned long long p) {
    float lo, hi;
    asm("mov.b64 {%0,%1}, %2;" : "=f"(lo), "=f"(hi) : "l"(p));
    return make_float2(lo, hi);
}

// ---------------- GEMM: g_I = g_xd (64000x704) * g_winT (704x1024) ----------------
// 128x128 tile, BK=16, 256 threads, 8x8 microtile split as rows tm..tm+7 ×
// cols {tn..tn+3, tn+64..tn+67} (conflict-free Bs LDS.128 phases).
#define ASTRIDE 132   // 132 % 32 = 4 -> As STS conflicts 4-way -> 2-way

__global__ void __launch_bounds__(256, 2) gemm_kernel() {
    __shared__ float As[2][16][ASTRIDE];
    __shared__ float Bs[2][16][128];
    int tid = threadIdx.x;
    int mBase = blockIdx.y * 128;
    int nBase = blockIdx.x * 128;
    const float* Ag = g_xd  + (size_t)mBase * CP_;
    const float* Bg = g_winT + nBase;

    int arow = tid >> 2;           // 0..63  (row within 128-tile, +64 for second)
    int akc  = (tid & 3) * 4;      // k offset (float) within 16
    int bk   = tid >> 5;           // 0..7   (k row, +8 for second)
    int bc   = (tid & 31) * 4;     // n offset

    float4 a0v, a1v, b0v, b1v;
    a0v = *(const float4*)(Ag + (size_t)arow      * CP_ + akc);
    a1v = *(const float4*)(Ag + (size_t)(arow+64) * CP_ + akc);
    b0v = *(const float4*)(Bg + (size_t)bk      * H_ + bc);
    b1v = *(const float4*)(Bg + (size_t)(bk+8)  * H_ + bc);

    As[0][akc+0][arow] = a0v.x; As[0][akc+1][arow] = a0v.y;
    As[0][akc+2][arow] = a0v.z; As[0][akc+3][arow] = a0v.w;
    As[0][akc+0][arow+64] = a1v.x; As[0][akc+1][arow+64] = a1v.y;
    As[0][akc+2][arow+64] = a1v.z; As[0][akc+3][arow+64] = a1v.w;
    *(float4*)&Bs[0][bk][bc]   = b0v;
    *(float4*)&Bs[0][bk+8][bc] = b1v;
    __syncthreads();

    unsigned long long acc[8][4];
#pragma unroll
    for (int i = 0; i < 8; i++)
#pragma unroll
        for (int j = 0; j < 4; j++) acc[i][j] = 0ull;

    int tn = (tid & 15) * 4;       // cols tn..tn+3 and tn+64..tn+67
    int tm = (tid >> 4) * 8;

    const int KT = CP_ / 16;   // 44
    for (int kt = 0; kt < KT; kt++) {
        int cur = kt & 1;
        if (kt + 1 < KT) {
            int k0 = (kt + 1) * 16;
            a0v = *(const float4*)(Ag + (size_t)arow      * CP_ + k0 + akc);
            a1v = *(const float4*)(Ag + (size_t)(arow+64) * CP_ + k0 + akc);
            b0v = *(const float4*)(Bg + (size_t)(k0+bk)   * H_ + bc);
            b1v = *(const float4*)(Bg + (size_t)(k0+bk+8) * H_ + bc);
        }
#pragma unroll
        for (int kk = 0; kk < 16; kk++) {
            float4 af0 = *(const float4*)&As[cur][kk][tm];
            float4 af1 = *(const float4*)&As[cur][kk][tm+4];
            float4 bf0 = *(const float4*)&Bs[cur][kk][tn];
            float4 bf1 = *(const float4*)&Bs[cur][kk][tn+64];
            unsigned long long bp0 = pk2(bf0.x, bf0.y);
            unsigned long long bp1 = pk2(bf0.z, bf0.w);
            unsigned long long bp2 = pk2(bf1.x, bf1.y);
            unsigned long long bp3 = pk2(bf1.z, bf1.w);
            float aa[8] = {af0.x, af0.y, af0.z, af0.w, af1.x, af1.y, af1.z, af1.w};
#pragma unroll
            for (int i = 0; i < 8; i++) {
                unsigned long long ad = pk2(aa[i], aa[i]);
                fma2(acc[i][0], ad, bp0);
                fma2(acc[i][1], ad, bp1);
                fma2(acc[i][2], ad, bp2);
                fma2(acc[i][3], ad, bp3);
            }
        }
        if (kt + 1 < KT) {
            int nxt = cur ^ 1;
            As[nxt][akc+0][arow] = a0v.x; As[nxt][akc+1][arow] = a0v.y;
            As[nxt][akc+2][arow] = a0v.z; As[nxt][akc+3][arow] = a0v.w;
            As[nxt][akc+0][arow+64] = a1v.x; As[nxt][akc+1][arow+64] = a1v.y;
            As[nxt][akc+2][arow+64] = a1v.z; As[nxt][akc+3][arow+64] = a1v.w;
            *(float4*)&Bs[nxt][bk][bc]   = b0v;
            *(float4*)&Bs[nxt][bk+8][bc] = b1v;
            __syncthreads();
        }
    }

    // streaming (evict-first) stores: g_I written once, read once later.
    float* Cg = g_I + (size_t)(mBase + tm) * H_ + nBase;
#pragma unroll
    for (int i = 0; i < 8; i++) {
        float2 r0 = upk2(acc[i][0]), r1 = upk2(acc[i][1]);
        float2 r2 = upk2(acc[i][2]), r3 = upk2(acc[i][3]);
        __stcs((float4*)(Cg + (size_t)i * H_ + tn),
               make_float4(r0.x, r0.y, r1.x, r1.y));
        __stcs((float4*)(Cg + (size_t)i * H_ + tn + 64),
               make_float4(r2.x, r2.y, r3.x, r3.y));
    }
}

// ---------------- recurrent scan: one CTA per batch sample ----------------
// 256 threads, each owns 4 neurons (float4 state). Spikes compacted by ALL
// threads into a counted, h-sorted index list (double-buffered). Rec input:
// per spike j one LDG.128 of w_recT[j][h0..h0+3], 8-way MLP. Output layer is
// list-driven on pre-transposed w_outT with width-8 shfl reduction.
__device__ __forceinline__ void add4(float4& a, float4 b) {
    a.x += b.x; a.y += b.y; a.z += b.z; a.w += b.w;
}

__global__ void __launch_bounds__(256) rec_kernel(
    const float* __restrict__ alpha,  const float* __restrict__ rho,
    const float* __restrict__ beta_a, const float* __restrict__ beta_out,
    float* __restrict__ out) {
    __shared__ alignas(16) short slist[2][H_];
    __shared__ int scnt[2];
    __shared__ int wtot[8];

    int tid = threadIdx.x, b = blockIdx.x;
    int lane = tid & 31, wid = tid >> 5;
    int h0 = tid * 4;

    float4 al4 = *(const float4*)(alpha  + h0);
    float4 rh4 = *(const float4*)(rho    + h0);
    float4 ba4 = *(const float4*)(beta_a + h0);

    int o_ = wid * 4 + (lane >> 3);            // valid for wid < 5
    float bo = 0.f, one_bo = 0.f;
    if (wid < 5) { bo = __ldg(&beta_out[o_]); one_bo = 1.f - bo; }

    float4 v4  = make_float4(0,0,0,0);
    float4 a4  = make_float4(0,0,0,0);
    float4 sp4 = make_float4(0,0,0,0);
    float vo = 0.f, osum = 0.f;
    if (tid < 2) scnt[tid] = 0;
    __syncthreads();

    const float4* Ib4 = (const float4*)(g_I + (size_t)b * T_ * H_) + tid;
    const float4* Wr4 = (const float4*)g_wrecT + tid;   // + j*256 selects row j

    float4 Icur = __ldcs(Ib4);

    for (int t = 0; t < T_; t++) {
        int wbuf = t & 1, rbuf = wbuf ^ 1;
        float4 Inxt = make_float4(0,0,0,0);
        if (t + 1 < T_) Inxt = __ldcs(Ib4 + (size_t)(t + 1) * (H_ / 4));

        float4 acc = Icur;
        int cnt = scnt[rbuf];
        if (cnt > 0) {
            float4 A0 = make_float4(0,0,0,0), A1 = A0, A2 = A0, A3 = A0;
            float4 A4 = A0, A5 = A0, A6 = A0, A7 = A0;
            int j = 0;
            for (; j + 8 <= cnt; j += 8) {
                int4 pk = *(const int4*)&slist[rbuf][j];
                int j0 =  pk.x        & 0xFFFF, j1 = (pk.x >> 16) & 0xFFFF;
                int j2 =  pk.y        & 0xFFFF, j3 = (pk.y >> 16) & 0xFFFF;
                int j4 =  pk.z        & 0xFFFF, j5 = (pk.z >> 16) & 0xFFFF;
                int j6 =  pk.w        & 0xFFFF, j7 = (pk.w >> 16) & 0xFFFF;
                add4(A0, __ldg(Wr4 + j0 * 256));
                add4(A1, __ldg(Wr4 + j1 * 256));
                add4(A2, __ldg(Wr4 + j2 * 256));
                add4(A3, __ldg(Wr4 + j3 * 256));
                add4(A4, __ldg(Wr4 + j4 * 256));
                add4(A5, __ldg(Wr4 + j5 * 256));
                add4(A6, __ldg(Wr4 + j6 * 256));
                add4(A7, __ldg(Wr4 + j7 * 256));
            }
#pragma unroll 1
            for (; j < cnt; j++)
                add4(A0, __ldg(Wr4 + (int)slist[rbuf][j] * 256));
            add4(A0, A1); add4(A2, A3); add4(A4, A5); add4(A6, A7);
            add4(A0, A2); add4(A4, A6); add4(A0, A4);
            add4(acc, A0);
        }

        // adaptive LIF update (reference expression order, per component)
        float4 v1n, sn;
        v1n.x = al4.x * v4.x * (1.f - sp4.x) + (1.f - al4.x) * (acc.x - a4.x);
        v1n.y = al4.y * v4.y * (1.f - sp4.y) + (1.f - al4.y) * (acc.y - a4.y);
        v1n.z = al4.z * v4.z * (1.f - sp4.z) + (1.f - al4.z) * (acc.z - a4.z);
        v1n.w = al4.w * v4.w * (1.f - sp4.w) + (1.f - al4.w) * (acc.w - a4.w);
        sn.x = ((v1n.x - 1.0f) > 0.f) ? 1.f : 0.f;
        sn.y = ((v1n.y - 1.0f) > 0.f) ? 1.f : 0.f;
        sn.z = ((v1n.z - 1.0f) > 0.f) ? 1.f : 0.f;
        sn.w = ((v1n.w - 1.0f) > 0.f) ? 1.f : 0.f;
        a4.x = rh4.x * a4.x + (1.f - rh4.x) * (ba4.x * v1n.x + sn.x);
        a4.y = rh4.y * a4.y + (1.f - rh4.y) * (ba4.y * v1n.y + sn.y);
        a4.z = rh4.z * a4.z + (1.f - rh4.z) * (ba4.z * v1n.z + sn.z);
        a4.w = rh4.w * a4.w + (1.f - rh4.w) * (ba4.w * v1n.w + sn.w);
        v4 = v1n; sp4 = sn;

        // compaction: 4 spike bits per thread -> h-sorted list in slist[wbuf]
        unsigned m4 = (sn.x != 0.f ? 1u : 0u) | (sn.y != 0.f ? 2u : 0u)
                    | (sn.z != 0.f ? 4u : 0u) | (sn.w != 0.f ? 8u : 0u);
        int c = __popc(m4);
        int pre = c;
#pragma unroll
        for (int off = 1; off < 32; off <<= 1) {
            int y = __shfl_up_sync(0xffffffffu, pre, off);
            if (lane >= off) pre += y;
        }
        if (lane == 31) wtot[wid] = pre;
        __syncthreads();                       // S1: warp totals visible
        int woff = 0, tot = 0;
#pragma unroll
        for (int w = 0; w < 8; w++) {
            int tw = wtot[w];
            if (w < wid) woff += tw;
            tot += tw;
        }
        int k = woff + (pre - c);
        unsigned mm = m4;
        while (mm) {
            int bit = __ffs(mm) - 1;
            mm &= mm - 1;
            slist[wbuf][k++] = (short)(h0 + bit);
        }
        if (tid == 0) scnt[wbuf] = tot;
        __syncthreads();                       // S2: list complete

        // output layer: warps 0..4, 8 lanes per output o, list-driven
        if (wid < 5) {
            float io = 0.f;
            for (int j = lane & 7; j < tot; j += 8)
                io += __ldg(&g_woutT[(int)slist[wbuf][j] * O_ + o_]);
            io += __shfl_down_sync(0xffffffffu, io, 4, 8);
            io += __shfl_down_sync(0xffffffffu, io, 2, 8);
            io += __shfl_down_sync(0xffffffffu, io, 1, 8);
            if ((lane & 7) == 0) { vo = bo * vo + one_bo * io; osum += vo; }
        }
        Icur = Inxt;
    }
    if (wid < 5 && (lane & 7) == 0) out[b * O_ + o_] = osum / (float)T_;
}

// ---------------- launch ----------------
extern "C" void kernel_launch(void* const* d_in, const int* in_sizes, int n_in,
                              void* d_out, int out_size) {
    const float* x        = (const float*)d_in[0];
    const int*   delays   = (const int*)  d_in[1];
    const float* w_in     = (const float*)d_in[2];
    const float* w_rec    = (const float*)d_in[3];
    const float* w_out    = (const float*)d_in[4];
    const float* alpha    = (const float*)d_in[5];
    const float* rho      = (const float*)d_in[6];
    const float* beta_a   = (const float*)d_in[7];
    const float* beta_out = (const float*)d_in[8];
    float* out = (float*)d_out;

    int prep_n = CP_ * H_ + H_ * H_ + H_ * O_;
    prep_kernel  <<<(prep_n + 511) / 512, 512>>>(w_in, w_rec, w_out);
    gather_kernel<<<(M_ * (CP_ / 4) + 511) / 512, 512>>>(x, delays);
    gemm_kernel  <<<dim3(8, 500), 256>>>();
    rec_kernel   <<<B_, 256>>>(alpha, rho, beta_a, beta_out, out);
}